// round 14
// baseline (speedup 1.0000x reference)
#include <cuda_runtime.h>
#include <float.h>

// Fused MaxPool(2x2,s1,SAME) -> depthwise 3x3 binomial blur -> AvgPool(2x2,s2)
// == separable 4x4 stencil w=(1,3,3,1)/8 stride 2 over maxpool output y.
//
// R13: R3's proven strip body VERBATIM (double-buffered column pairs, 14-load
// 256B bursts, predicated-select boundaries, 128-reg natural codegen), made
// persistent: exactly 4 CTAs/SM, each warp pops strip indices from a global
// atomic counter. Kills wave transitions + launch/drain churn; perfect
// +-1-strip load balance. Counter reset by a 1-thread kernel each launch
// (two launches, both graph-capturable; no allocations).

#define NROWP  28
#define ROWSTR (112*64)     // float2 per x row
#define PXSTR  64           // float2 per pixel
#define NSTRIP 7168u        // 32 b * 28 row-pairs * 4 col chunks * 2 ch halves

__device__ unsigned int g_strip_ctr;

__global__ void reset_ctr_kernel() { g_strip_ctr = 0u; }

__device__ __forceinline__ float2 f2max(float2 a, float2 b) {
    return make_float2(fmaxf(a.x,b.x), fmaxf(a.y,b.y));
}
__device__ __forceinline__ void f2fma(float2& a, float w, float2 v) {
    a.x = fmaf(w, v.x, a.x); a.y = fmaf(w, v.y, a.y);
}

// Load 7 x-rows of one column. Rows 1..4 always in range; row 0 invalid only
// for the top strip, rows 5,6 invalid only for the bottom strip.
#define LOADCOL(dst, c, cOk) do {                                         \
    const float2* _p = base + (long long)(c) * PXSTR;                     \
    dst[0] = ((cOk) && okTop) ? __ldg(_p)              : NEG;             \
    dst[1] = (cOk) ? __ldg(_p + 1*ROWSTR) : NEG;                          \
    dst[2] = (cOk) ? __ldg(_p + 2*ROWSTR) : NEG;                          \
    dst[3] = (cOk) ? __ldg(_p + 3*ROWSTR) : NEG;                          \
    dst[4] = (cOk) ? __ldg(_p + 4*ROWSTR) : NEG;                          \
    dst[5] = ((cOk) && okBot) ? __ldg(_p + 5*ROWSTR) : NEG;               \
    dst[6] = ((cOk) && okBot) ? __ldg(_p + 6*ROWSTR) : NEG;               \
} while (0)

// Finalize one y column (TY literal after unroll): vertical (1,3,3,1)/8
// reduction then scatter into the two pending output-column accumulators.
#define STEP(prevcm, curcm, TY) do {                                      \
    const bool _skip = ((TY)==0 && leftSkip) || ((TY)==29 && rightSkip);  \
    if (!_skip) {                                                         \
        float2 yc[6];                                                     \
        _Pragma("unroll")                                                 \
        for (int _k = 0; _k < 6; _k++) yc[_k] = f2max(prevcm[_k], curcm[_k]); \
        if (!okTop) yc[0] = ZERO;                                         \
        if (!okBot) yc[5] = ZERO;                                         \
        const int   _m  = (TY) >> 1;                                      \
        const float _wA = ((TY) & 1) ? wv1 : wv0;                         \
        const float _wB = ((TY) & 1) ? wv0 : wv1;                         \
        _Pragma("unroll")                                                 \
        for (int _rl = 0; _rl < 2; _rl++) {                               \
            float2 V = ZERO;                                              \
            f2fma(V, wv0, yc[2*_rl + 0]);                                 \
            f2fma(V, wv1, yc[2*_rl + 1]);                                 \
            f2fma(V, wv1, yc[2*_rl + 2]);                                 \
            f2fma(V, wv0, yc[2*_rl + 3]);                                 \
            if (_m < 14) f2fma(acc[_rl][_m & 1], _wA, V);                 \
            if (_m >= 1) f2fma(acc[_rl][(_m & 1) ^ 1], _wB, V);           \
        }                                                                 \
    }                                                                     \
} while (0)

__global__ void __launch_bounds__(128, 4)
mbp_kernel(const float2* __restrict__ x, float2* __restrict__ out) {
    const int lane = threadIdx.x;
    const float2 NEG  = make_float2(-FLT_MAX, -FLT_MAX);
    const float2 ZERO = make_float2(0.f, 0.f);
    const float wv0 = 0.125f, wv1 = 0.375f;            // (1,3,3,1)/8

    for (;;) {
        // Warp-collective pop of the next strip index.
        unsigned s = 0;
        if (lane == 0) s = atomicAdd(&g_strip_ctr, 1u);
        s = __shfl_sync(0xffffffffu, s, 0);
        if (s >= NSTRIP) return;

        // ----- R3 strip body, verbatim, indices derived from s -----
        const int chHalf = (int)s & 1;
        const int strip  = (int)s >> 1;                // 3584 strips
        const int cj = strip & 3;                      // 4 col chunks of 14
        const int s2 = strip >> 2;
        const int ti = s2 % NROWP;                     // 28 row pairs
        const int b  = s2 / NROWP;

        const int oi0 = 2 * ti;
        const int oj0 = 14 * cj;
        const int xr0 = 4 * ti - 1;
        const int xc0 = 28 * cj - 1;

        const bool okTop     = (ti != 0);
        const bool okBot     = (ti != NROWP - 1);
        const bool leftSkip  = (cj == 0);
        const bool rightSkip = (cj == 3);

        const float2* base = x + (size_t)b * 112 * 112 * 64 + chHalf * 32
                               + lane + (long long)xr0 * ROWSTR;

        // Prime column xc0 -> cmPrev (column pair-maxes over x rows k,k+1)
        float2 cmPrev[6];
        {
            float2 xv[7];
            LOADCOL(xv, xc0, !leftSkip);               // xc0 < 0 only if cj==0
#pragma unroll
            for (int k = 0; k < 6; k++) cmPrev[k] = f2max(xv[k], xv[k+1]);
        }

        float2 acc[2][2];                              // [row][col&1] ring
        acc[0][0]=ZERO; acc[0][1]=ZERO; acc[1][0]=ZERO; acc[1][1]=ZERO;

        float2* ob = out + ((size_t)(b * 56 + oi0) * 56 + oj0) * 64
                         + chHalf * 32 + lane;

        // Double-buffered column pairs: buffer i&1 holds cols of iteration i.
        float2 xa[2][7], xb2[2][7];
        LOADCOL(xa[0],  xc0 + 1, true);
        LOADCOL(xb2[0], xc0 + 2, true);

#pragma unroll
        for (int i = 0; i < 15; i++) {
            const int cur = i & 1, nxt = cur ^ 1;
            if (i < 14) {                              // 14-load burst, iter i+1
                const bool ok = (i < 13) || !rightSkip;  // only cols 112/113 bad
                LOADCOL(xa[nxt],  xc0 + 3 + 2*i, ok);
                LOADCOL(xb2[nxt], xc0 + 4 + 2*i, ok);
            }

            float2 cmA[6], cmB[6];
#pragma unroll
            for (int k = 0; k < 6; k++) {
                cmA[k] = f2max(xa[cur][k],  xa[cur][k+1]);
                cmB[k] = f2max(xb2[cur][k], xb2[cur][k+1]);
            }

            STEP(cmPrev, cmA, 2*i);                    // y col ty = 2i
            STEP(cmA,    cmB, 2*i + 1);                // y col ty = 2i+1

            if (i >= 1) {                              // out col i-1 complete
                const int wl = i - 1, slot = wl & 1;
#pragma unroll
                for (int rl = 0; rl < 2; rl++) {
                    ob[((size_t)rl * 56 + wl) * 64] = acc[rl][slot];
                    acc[rl][slot] = ZERO;
                }
            }

#pragma unroll
            for (int k = 0; k < 6; k++) cmPrev[k] = cmB[k];
        }
        // ----- end strip body -----
    }
}

extern "C" void kernel_launch(void* const* d_in, const int* in_sizes, int n_in,
                              void* d_out, int out_size) {
    const float2* x = (const float2*)d_in[0];   // (32,112,112,128) f32
    // d_in[1] = blur kernel, baked into (1,3,3,1)/8
    float2* out = (float2*)d_out;               // (32,56,56,128) f32

    int nsm = 148;
    cudaDeviceGetAttribute(&nsm, cudaDevAttrMultiProcessorCount, 0);
    int grid = nsm * 4;                         // 4 CTAs/SM, exactly 1 wave
    if (grid > 1792) grid = 1792;               // never more CTAs than work

    reset_ctr_kernel<<<1, 1>>>();
    mbp_kernel<<<grid, dim3(32, 4)>>>(x, out);
}

// round 16
// speedup vs baseline: 1.1726x; 1.1726x over previous
#include <cuda_runtime.h>
#include <float.h>
#include <stdint.h>

// Fused MaxPool(2x2,s1,SAME) -> depthwise 3x3 binomial blur -> AvgPool(2x2,s2)
// == separable 4x4 stencil w=(1,3,3,1)/8 stride 2 over maxpool output y.
//
// R15: R3's exact pipeline (double-buffered column pairs, 14-load 256B
// bursts, (128,4), 1792 CTAs) with the FMA chain in packed f32x2
// (fma.rn.f32x2 / mul.rn.f32x2 -- the packed ops this toolkit supports;
// max.f32x2 does not exist, maxes stay scalar FMNMX). Pack/unpack is
// mov.b64 register-pair aliasing = free in SASS. 24 scalar FFMA/iter -> 12
// packed ops; arithmetic bit-identical.

#define NROWP  28
#define ROWSTR (112*64)     // float2 per x row
#define PXSTR  64           // float2 per pixel

// Packed weights: two identical fp32 halves of 0.125f / 0.375f.
#define W0P   0x3E0000003E000000ULL
#define W1P   0x3EC000003EC00000ULL

__device__ __forceinline__ float2 f2max(float2 a, float2 b) {
    return make_float2(fmaxf(a.x,b.x), fmaxf(a.y,b.y));
}
__device__ __forceinline__ uint64_t pk(float2 v) {      // free (reg aliasing)
    uint64_t r;
    asm("mov.b64 %0, {%1, %2};" : "=l"(r) : "f"(v.x), "f"(v.y));
    return r;
}
__device__ __forceinline__ uint64_t pmul(uint64_t a, uint64_t b) {
    uint64_t d;
    asm("mul.rn.f32x2 %0, %1, %2;" : "=l"(d) : "l"(a), "l"(b));
    return d;
}
__device__ __forceinline__ uint64_t pfma(uint64_t a, uint64_t b, uint64_t c) {
    uint64_t d;
    asm("fma.rn.f32x2 %0, %1, %2, %3;" : "=l"(d) : "l"(a), "l"(b), "l"(c));
    return d;
}

// Load 7 x-rows of one column. Rows 1..4 always in range; row 0 invalid only
// for the top strip, rows 5,6 invalid only for the bottom strip.
#define LOADCOL(dst, c, cOk) do {                                         \
    const float2* _p = base + (long long)(c) * PXSTR;                     \
    dst[0] = ((cOk) && okTop) ? __ldg(_p)              : NEG;             \
    dst[1] = (cOk) ? __ldg(_p + 1*ROWSTR) : NEG;                          \
    dst[2] = (cOk) ? __ldg(_p + 2*ROWSTR) : NEG;                          \
    dst[3] = (cOk) ? __ldg(_p + 3*ROWSTR) : NEG;                          \
    dst[4] = (cOk) ? __ldg(_p + 4*ROWSTR) : NEG;                          \
    dst[5] = ((cOk) && okBot) ? __ldg(_p + 5*ROWSTR) : NEG;               \
    dst[6] = ((cOk) && okBot) ? __ldg(_p + 6*ROWSTR) : NEG;               \
} while (0)

// Finalize one y column (TY literal after unroll): scalar maxes build yc,
// then the whole (1,3,3,1)/8 vertical + horizontal chain runs packed.
#define STEP(prevcm, curcm, TY) do {                                      \
    const bool _skip = ((TY)==0 && leftSkip) || ((TY)==29 && rightSkip);  \
    if (!_skip) {                                                         \
        float2 yc[6];                                                     \
        _Pragma("unroll")                                                 \
        for (int _k = 0; _k < 6; _k++) yc[_k] = f2max(prevcm[_k], curcm[_k]); \
        if (!okTop) yc[0] = ZERO;                                         \
        if (!okBot) yc[5] = ZERO;                                         \
        const int      _m  = (TY) >> 1;                                   \
        const uint64_t _wA = ((TY) & 1) ? W1P : W0P;                      \
        const uint64_t _wB = ((TY) & 1) ? W0P : W1P;                      \
        _Pragma("unroll")                                                 \
        for (int _rl = 0; _rl < 2; _rl++) {                               \
            uint64_t V = pmul(pk(yc[2*_rl + 0]), W0P);                    \
            V = pfma(pk(yc[2*_rl + 1]), W1P, V);                          \
            V = pfma(pk(yc[2*_rl + 2]), W1P, V);                          \
            V = pfma(pk(yc[2*_rl + 3]), W0P, V);                          \
            if (_m < 14) acc[_rl][_m & 1] = pfma(V, _wA, acc[_rl][_m & 1]); \
            if (_m >= 1) acc[_rl][(_m & 1) ^ 1] =                         \
                pfma(V, _wB, acc[_rl][(_m & 1) ^ 1]);                     \
        }                                                                 \
    }                                                                     \
} while (0)

__global__ void __launch_bounds__(128, 4)
mbp_kernel(const float2* __restrict__ x, uint64_t* __restrict__ out) {
    const int lane   = threadIdx.x;
    const int wid    = blockIdx.x * 4 + threadIdx.y;   // 7168 warp tasks
    const int chHalf = wid & 1;
    const int strip  = wid >> 1;                       // 3584 strips
    const int cj = strip & 3;                          // 4 col chunks of 14
    const int s2 = strip >> 2;
    const int ti = s2 % NROWP;                         // 28 row pairs
    const int b  = s2 / NROWP;

    const int oi0 = 2 * ti;
    const int oj0 = 14 * cj;
    const int xr0 = 4 * ti - 1;
    const int xc0 = 28 * cj - 1;

    const float2 NEG  = make_float2(-FLT_MAX, -FLT_MAX);
    const float2 ZERO = make_float2(0.f, 0.f);

    const bool okTop     = (ti != 0);
    const bool okBot     = (ti != NROWP - 1);
    const bool leftSkip  = (cj == 0);
    const bool rightSkip = (cj == 3);

    const float2* base = x + (size_t)b * 112 * 112 * 64 + chHalf * 32 + lane
                           + (long long)xr0 * ROWSTR;

    // Prime column xc0 -> cmPrev (column pair-maxes over x rows k,k+1)
    float2 cmPrev[6];
    {
        float2 xv[7];
        LOADCOL(xv, xc0, !leftSkip);                   // xc0 < 0 only if cj==0
#pragma unroll
        for (int k = 0; k < 6; k++) cmPrev[k] = f2max(xv[k], xv[k+1]);
    }

    uint64_t acc[2][2];                                // packed [row][col&1]
    acc[0][0]=0; acc[0][1]=0; acc[1][0]=0; acc[1][1]=0;

    uint64_t* ob = out + ((size_t)(b * 56 + oi0) * 56 + oj0) * 64
                       + chHalf * 32 + lane;

    // Double-buffered column pairs: buffer i&1 holds cols of iteration i.
    float2 xa[2][7], xb2[2][7];
    LOADCOL(xa[0],  xc0 + 1, true);
    LOADCOL(xb2[0], xc0 + 2, true);

#pragma unroll
    for (int i = 0; i < 15; i++) {
        const int cur = i & 1, nxt = cur ^ 1;
        if (i < 14) {                                  // 14-load burst, iter i+1
            const bool ok = (i < 13) || !rightSkip;    // only cols 112/113 bad
            LOADCOL(xa[nxt],  xc0 + 3 + 2*i, ok);
            LOADCOL(xb2[nxt], xc0 + 4 + 2*i, ok);
        }

        float2 cmA[6], cmB[6];
#pragma unroll
        for (int k = 0; k < 6; k++) {
            cmA[k] = f2max(xa[cur][k],  xa[cur][k+1]);
            cmB[k] = f2max(xb2[cur][k], xb2[cur][k+1]);
        }

        STEP(cmPrev, cmA, 2*i);                        // y col ty = 2i
        STEP(cmA,    cmB, 2*i + 1);                    // y col ty = 2i+1

        if (i >= 1) {                                  // out col i-1 complete
            const int wl = i - 1, slot = wl & 1;
#pragma unroll
            for (int rl = 0; rl < 2; rl++) {
                ob[((size_t)rl * 56 + wl) * 64] = acc[rl][slot];
                acc[rl][slot] = 0;
            }
        }

#pragma unroll
        for (int k = 0; k < 6; k++) cmPrev[k] = cmB[k];
    }
}

extern "C" void kernel_launch(void* const* d_in, const int* in_sizes, int n_in,
                              void* d_out, int out_size) {
    const float2* x = (const float2*)d_in[0];   // (32,112,112,128) f32
    // d_in[1] = blur kernel, baked into (1,3,3,1)/8
    uint64_t* out = (uint64_t*)d_out;           // (32,56,56,128) f32

    // 3584 strips x 2 channel halves = 7168 warp tasks, 4 warps/CTA
    dim3 block(32, 4);
    dim3 grid(7168 / 4);                        // 1792 blocks
    mbp_kernel<<<grid, block>>>(x, out);
}